// round 13
// baseline (speedup 1.0000x reference)
#include <cuda_runtime.h>
#include <cstdint>
#include <math.h>

#define B   16
#define TK  2048
#define STK 64
#define N   512

// output layout (flattened tuple, row-major each)
#define OFF_CT    0
#define OFF_ATTN  (B*N)
#define OFF_COV   (OFF_ATTN + B*TK)
#define OFF_SCT   (OFF_COV + B*TK)
#define OFF_SATTN (OFF_SCT + B*N)

#define SC_SPLIT  32               // scorer blocks per b (64 tokens each)
#define NSCORE    (B*SC_SPLIT)     // 512
#define NSENT     16

// scratch
__device__ float g_dec[B*N];       // word decoder features
__device__ float g_sdec[B*N];      // sentence decoder features
__device__ float g_e[B*TK];        // exp(score)*mask
__device__ float g_S[B];           // sum of e per b
__device__ float g_segsum[B*STK];  // per-sentence sums of e

__device__ __forceinline__ float warp_sum(float v)
{
#pragma unroll
    for (int o = 16; o; o >>= 1) v += __shfl_xor_sync(0xffffffffu, v, o);
    return v;
}
__device__ __forceinline__ float warp_max(float v)
{
#pragma unroll
    for (int o = 16; o; o >>= 1) v = fmaxf(v, __shfl_xor_sync(0xffffffffu, v, o));
    return v;
}
__device__ __forceinline__ float dot4(float4 a, float4 b)
{
    return fmaf(a.x, b.x, fmaf(a.y, b.y, fmaf(a.z, b.z, a.w * b.w)));
}
__device__ __forceinline__ float tanh_fast(float x)
{
    float y;
    asm("tanh.approx.f32 %0, %1;" : "=f"(y) : "f"(x));
    return y;
}
__device__ __forceinline__ int seg_of(int t, const int* pos)
{
    int lo = 0, hi = STK;
    while (lo < hi) {
        int mid = (lo + hi) >> 1;
        if (pos[mid] <= t) lo = mid + 1; else hi = mid;
    }
    return lo;
}
__device__ __forceinline__ void cp_async16(void* smem_dst, const void* gmem_src)
{
    unsigned int d = (unsigned int)__cvta_generic_to_shared(smem_dst);
    asm volatile("cp.async.cg.shared.global [%0], [%1], 16;" :: "r"(d), "l"(gmem_src));
}
__device__ __forceinline__ void cp_commit()
{
    asm volatile("cp.async.commit_group;");
}
template <int K>
__device__ __forceinline__ void cp_wait()
{
    asm volatile("cp.async.wait_group %0;" :: "n"(K));
}

// ---------------------------------------------------------------------------
// Kernel 1: both dec GEMMs. grid 512, 256 thr. Warp: 1 row x 4 b.
// 4 independent accumulators, interleaved shuffle reductions.
// Also zeroes g_S, g_segsum, o_ct (distributed).
// ---------------------------------------------------------------------------
__global__ void dec_gemm(const float* __restrict__ s_word,
                         const float* __restrict__ Wd,
                         const float* __restrict__ bd,
                         const float* __restrict__ s_sent,
                         const float* __restrict__ Wsd,
                         const float* __restrict__ bsd,
                         float* __restrict__ o_ct)
{
    int blk  = blockIdx.x;            // 0..511
    int tid  = threadIdx.x;
    int wid  = tid >> 5;
    int lane = tid & 31;

    int g = blk * 256 + tid;
    if (g < B * N)   o_ct[g] = 0.f;
    if (g < B * STK) g_segsum[g] = 0.f;
    if (g < B)       g_S[g] = 0.f;

    int which = blk >> 8;             // 0 word, 1 sentence
    int rem   = blk & 255;
    const float* W    = which ? Wsd    : Wd;
    const float* bias = which ? bsd    : bd;
    const float* s    = which ? s_sent : s_word;
    float*       dst  = which ? g_sdec : g_dec;

    int n  = rem * 2 + (wid >> 2);
    int b0 = (wid & 3) * 4;

    const float4* wv = (const float4*)(W + (size_t)n * N);
    float4 w0 = wv[lane], w1 = wv[32+lane], w2 = wv[64+lane], w3 = wv[96+lane];
    float bn = bias[n];

    float a0, a1, a2, a3;
    {
        const float4* s0 = (const float4*)(s + (size_t)(b0 + 0) * N);
        const float4* s1 = (const float4*)(s + (size_t)(b0 + 1) * N);
        const float4* s2 = (const float4*)(s + (size_t)(b0 + 2) * N);
        const float4* s3 = (const float4*)(s + (size_t)(b0 + 3) * N);
        a0 = dot4(s0[lane],w0)+dot4(s0[32+lane],w1)+dot4(s0[64+lane],w2)+dot4(s0[96+lane],w3);
        a1 = dot4(s1[lane],w0)+dot4(s1[32+lane],w1)+dot4(s1[64+lane],w2)+dot4(s1[96+lane],w3);
        a2 = dot4(s2[lane],w0)+dot4(s2[32+lane],w1)+dot4(s2[64+lane],w2)+dot4(s2[96+lane],w3);
        a3 = dot4(s3[lane],w0)+dot4(s3[32+lane],w1)+dot4(s3[64+lane],w2)+dot4(s3[96+lane],w3);
    }
#pragma unroll
    for (int o = 16; o; o >>= 1) {
        a0 += __shfl_xor_sync(0xffffffffu, a0, o);
        a1 += __shfl_xor_sync(0xffffffffu, a1, o);
        a2 += __shfl_xor_sync(0xffffffffu, a2, o);
        a3 += __shfl_xor_sync(0xffffffffu, a3, o);
    }
    if (lane == 0) {
        dst[(b0 + 0) * N + n] = a0 + bn;
        dst[(b0 + 1) * N + n] = a1 + bn;
        dst[(b0 + 2) * N + n] = a2 + bn;
        dst[(b0 + 3) * N + n] = a3 + bn;
    }
}

// ---------------------------------------------------------------------------
// Kernel 2: scorer with cp.async double-buffered feat rows.
// blocks [0,512): 64 tokens of b; warp owns 8 tokens; each lane copies its
// own 4 float4 chunks per row into warp-private smem (no cross-lane sharing,
// so no syncs). blocks [512,528): sentence path.
// ---------------------------------------------------------------------------
__global__ void __launch_bounds__(256, 5)
score_big(const float* __restrict__ feat,
          const float* __restrict__ v,
          const float* __restrict__ wc,
          const float* __restrict__ cov,
          const float* __restrict__ mask,
          const int* __restrict__ spos,
          const float* __restrict__ sfeat,
          const float* __restrict__ svw,
          const float* __restrict__ smask,
          const float* __restrict__ sout,
          float* __restrict__ o_sattn,
          float* __restrict__ o_sct)
{
    __shared__ float4 s_d[N/4];            // 2KB
    __shared__ float4 s_V[N/4];            // 2KB
    __shared__ float4 s_w[N/4];            // 2KB
    __shared__ float4 fbuf[2][8][N/4];     // 32KB: 2 stages x 8 warps x row
    __shared__ int    pos[STK];
    __shared__ float  warp_e[8];

    int blk  = blockIdx.x;
    int tid  = threadIdx.x;
    int wid  = tid >> 5;
    int lane = tid & 31;

    if (blk < NSCORE) {
        int b  = blk >> 5;                 // 32 blocks per b
        int t0 = (blk & 31) * 64;          // warp owns tokens t0+wid*8 .. +7

        {
            const float4* dv = (const float4*)(g_dec + (size_t)b * N);
            const float4* vv = (const float4*)v;
            const float4* wv = (const float4*)wc;
            if (tid < N/4) {
                s_d[tid] = dv[tid];
                s_V[tid] = vv[tid];
                s_w[tid] = wv[tid];
            } else {
                int i = tid - N/4;
                if (i < STK) pos[i] = spos[b * STK + i];
            }
        }
        __syncthreads();

        int tbase = t0 + wid * 8;
        const float4* frow0 = (const float4*)(feat + ((size_t)b * TK + tbase) * N);

        // prefetch row 0 into stage 0
#pragma unroll
        for (int j = 0; j < 4; j++)
            cp_async16(&fbuf[0][wid][j * 32 + lane], frow0 + j * 32 + lane);
        cp_commit();

        float esum = 0.f;
#pragma unroll
        for (int k = 0; k < 8; k++) {
            if (k < 7) {
                const float4* fr = frow0 + (size_t)(k + 1) * (N / 4);
                int st = (k + 1) & 1;
#pragma unroll
                for (int j = 0; j < 4; j++)
                    cp_async16(&fbuf[st][wid][j * 32 + lane], fr + j * 32 + lane);
                cp_commit();
                cp_wait<1>();              // row k ready
            } else {
                cp_wait<0>();
            }

            int t = tbase + k;
            int gidx = b * TK + t;
            float c = cov[gidx];
            const float4* fb = fbuf[k & 1][wid];

            float acc = 0.f;
#pragma unroll
            for (int j = 0; j < 4; j++) {
                int i = j * 32 + lane;
                float4 f = fb[i];
                float4 d = s_d[i];
                float4 V = s_V[i];
                float4 w = s_w[i];
                acc = fmaf(tanh_fast(f.x + d.x + c * w.x), V.x,
                      fmaf(tanh_fast(f.y + d.y + c * w.y), V.y,
                      fmaf(tanh_fast(f.z + d.z + c * w.z), V.z,
                      fmaf(tanh_fast(f.w + d.w + c * w.w), V.w, acc))));
            }
            acc = warp_sum(acc);

            if (lane == 0) {
                float e = expf(acc) * mask[gidx];
                g_e[gidx] = e;
                int sg = seg_of(t, pos);
                if (sg < STK) atomicAdd(&g_segsum[b * STK + sg], e);
                esum += e;
            }
        }
        if (lane == 0) warp_e[wid] = esum;
        __syncthreads();
        if (tid == 0) {
            float s = 0.f;
#pragma unroll
            for (int i = 0; i < 8; i++) s += warp_e[i];
            atomicAdd(&g_S[b], s);
        }
    } else {
        // ---------------- sentence path: one block per b ----------------
        __shared__ float se[STK];
        int b = blk - NSCORE;

        const float4* dv = (const float4*)(g_sdec + (size_t)b * N);
        const float4* vv = (const float4*)svw;
        for (int t = wid; t < STK; t += 8) {
            const float4* fv = (const float4*)(sfeat + ((size_t)b * STK + t) * N);
            float acc = 0.f;
#pragma unroll
            for (int i = 0; i < 4; i++) {
                int j = i * 32 + lane;
                float4 f = fv[j];
                float4 d = dv[j];
                float4 V = vv[j];
                acc = fmaf(tanh_fast(f.x + d.x), V.x,
                      fmaf(tanh_fast(f.y + d.y), V.y,
                      fmaf(tanh_fast(f.z + d.z), V.z,
                      fmaf(tanh_fast(f.w + d.w), V.w, acc))));
            }
            acc = warp_sum(acc);
            if (lane == 0) se[t] = acc;
        }
        __syncthreads();

        if (wid == 0) {
            float s0 = se[lane], s1 = se[lane + 32];
            float m = warp_max(fmaxf(s0, s1));
            float e0 = expf(s0 - m), e1 = expf(s1 - m);
            float inv = 1.f / warp_sum(e0 + e1);
            float a0 = e0 * inv * smask[b * STK + lane];
            float a1 = e1 * inv * smask[b * STK + 32 + lane];
            float inv2 = 1.f / warp_sum(a0 + a1);
            a0 *= inv2; a1 *= inv2;
            se[lane] = a0; se[lane + 32] = a1;
            o_sattn[b * STK + lane]      = a0;
            o_sattn[b * STK + 32 + lane] = a1;
        }
        __syncthreads();

        for (int n = tid; n < N; n += 256) {
            float acc = 0.f;
#pragma unroll 8
            for (int t = 0; t < STK; t++)
                acc = fmaf(se[t], sout[((size_t)b * STK + t) * N + n], acc);
            o_sct[b * N + n] = acc;
        }
    }
}

// ---------------------------------------------------------------------------
// Kernel 3: finalize attn/coverage + word context. grid (B,64), 256 thr.
// ---------------------------------------------------------------------------
__global__ void __launch_bounds__(256, 6)
ctx_big(const float* __restrict__ enc,
        const float* __restrict__ cov,
        const int* __restrict__ spos,
        const float* __restrict__ sattn,
        float* __restrict__ o_attn,
        float* __restrict__ o_cov,
        float* __restrict__ o_ct)
{
    __shared__ float sh_a[32];
    __shared__ int   pos[STK];
    __shared__ float ssum[STK];
    __shared__ float satt[STK];

    int b   = blockIdx.x;
    int t0  = blockIdx.y * 32;
    int tid = threadIdx.x;

    if (tid < STK) {
        pos[tid]  = spos[b * STK + tid];
        ssum[tid] = g_segsum[b * STK + tid];
        satt[tid] = sattn[b * STK + tid];
    }
    __syncthreads();

    float invS = 1.f / g_S[b];
    if (tid < 32) {
        int t = t0 + tid;
        float e = g_e[b * TK + t];
        float a = e * invS;
        sh_a[tid] = a;
        o_attn[b * TK + t] = a;
        int sg = seg_of(t, pos);
        float sw = (sg < STK) ? e / ssum[sg] * satt[sg] : 0.f;
        o_cov[b * TK + t] = cov[b * TK + t] + sw;
    }
    __syncthreads();

    int grp = tid >> 7;
    int col = tid & 127;
    const float4* ev = (const float4*)enc;
    size_t base = ((size_t)b * TK + t0 + grp * 16) * (N / 4) + col;
    float4 acc = make_float4(0.f, 0.f, 0.f, 0.f);
#pragma unroll
    for (int i = 0; i < 16; i++) {
        float a = sh_a[grp * 16 + i];
        float4 x = ev[base + (size_t)i * (N / 4)];
        acc.x = fmaf(a, x.x, acc.x);
        acc.y = fmaf(a, x.y, acc.y);
        acc.z = fmaf(a, x.z, acc.z);
        acc.w = fmaf(a, x.w, acc.w);
    }
    float* o = o_ct + (size_t)b * N + col * 4;
    atomicAdd(o + 0, acc.x);
    atomicAdd(o + 1, acc.y);
    atomicAdd(o + 2, acc.z);
    atomicAdd(o + 3, acc.w);
}

// ---------------------------------------------------------------------------
extern "C" void kernel_launch(void* const* d_in, const int* in_sizes, int n_in,
                              void* d_out, int out_size)
{
    const float* s_t_hat  = (const float*)d_in[0];
    const int*   spos     = (const int*)  d_in[1];
    const float* enc_out  = (const float*)d_in[2];
    const float* enc_feat = (const float*)d_in[3];
    const float* mask     = (const float*)d_in[4];
    const float* s_sent   = (const float*)d_in[5];
    const float* sout     = (const float*)d_in[6];
    const float* sfeat    = (const float*)d_in[7];
    const float* smask    = (const float*)d_in[8];
    const float* cov      = (const float*)d_in[9];
    const float* Wd       = (const float*)d_in[10];
    const float* bd       = (const float*)d_in[11];
    const float* vw       = (const float*)d_in[12];
    const float* Wsd      = (const float*)d_in[13];
    const float* bsd      = (const float*)d_in[14];
    const float* svw      = (const float*)d_in[15];
    const float* wc       = (const float*)d_in[16];

    float* out     = (float*)d_out;
    float* o_ct    = out + OFF_CT;
    float* o_attn  = out + OFF_ATTN;
    float* o_cov   = out + OFF_COV;
    float* o_sct   = out + OFF_SCT;
    float* o_sattn = out + OFF_SATTN;

    dec_gemm<<<512, 256>>>(s_t_hat, Wd, bd, s_sent, Wsd, bsd, o_ct);

    score_big<<<NSCORE + NSENT, 256>>>(enc_feat, vw, wc, cov, mask, spos,
                                       sfeat, svw, smask, sout, o_sattn, o_sct);

    ctx_big<<<dim3(B, 64), 256>>>(enc_out, cov, spos, o_sattn,
                                  o_attn, o_cov, o_ct);
}

// round 14
// speedup vs baseline: 1.3214x; 1.3214x over previous
#include <cuda_runtime.h>
#include <math.h>

#define B   16
#define TK  2048
#define STK 64
#define N   512

// output layout (flattened tuple, row-major each)
#define OFF_CT    0
#define OFF_ATTN  (B*N)
#define OFF_COV   (OFF_ATTN + B*TK)
#define OFF_SCT   (OFF_COV + B*TK)
#define OFF_SATTN (OFF_SCT + B*N)

#define SC_SPLIT  32               // scorer blocks per b (64 tokens each)
#define NSCORE    (B*SC_SPLIT)     // 512
#define NSENT     16

// scratch
__device__ float g_dec[B*N];       // word decoder features
__device__ float g_sdec[B*N];      // sentence decoder features
__device__ float g_e[B*TK];        // exp(score)*mask
__device__ float g_S[B];           // sum of e per b
__device__ float g_segsum[B*STK];  // per-sentence sums of e

__device__ __forceinline__ float warp_sum(float v)
{
#pragma unroll
    for (int o = 16; o; o >>= 1) v += __shfl_xor_sync(0xffffffffu, v, o);
    return v;
}
__device__ __forceinline__ float warp_max(float v)
{
#pragma unroll
    for (int o = 16; o; o >>= 1) v = fmaxf(v, __shfl_xor_sync(0xffffffffu, v, o));
    return v;
}
__device__ __forceinline__ float dot4(float4 a, float4 b)
{
    return fmaf(a.x, b.x, fmaf(a.y, b.y, fmaf(a.z, b.z, a.w * b.w)));
}
__device__ __forceinline__ float tanh_fast(float x)
{
    float y;
    asm("tanh.approx.f32 %0, %1;" : "=f"(y) : "f"(x));
    return y;
}
__device__ __forceinline__ int seg_of(int t, const int* pos)
{
    int lo = 0, hi = STK;
    while (lo < hi) {
        int mid = (lo + hi) >> 1;
        if (pos[mid] <= t) lo = mid + 1; else hi = mid;
    }
    return lo;
}

// ---------------------------------------------------------------------------
// Kernel 1: both dec GEMMs. grid 512, 256 thr. Warp: 1 row x 4 b.
// Also zeroes g_S, g_segsum, o_ct (distributed).
// ---------------------------------------------------------------------------
__global__ void dec_gemm(const float* __restrict__ s_word,
                         const float* __restrict__ Wd,
                         const float* __restrict__ bd,
                         const float* __restrict__ s_sent,
                         const float* __restrict__ Wsd,
                         const float* __restrict__ bsd,
                         float* __restrict__ o_ct)
{
    int blk  = blockIdx.x;            // 0..511
    int tid  = threadIdx.x;
    int wid  = tid >> 5;
    int lane = tid & 31;

    int g = blk * 256 + tid;
    if (g < B * N)   o_ct[g] = 0.f;
    if (g < B * STK) g_segsum[g] = 0.f;
    if (g < B)       g_S[g] = 0.f;

    int which = blk >> 8;             // 0 word, 1 sentence
    int rem   = blk & 255;
    const float* W    = which ? Wsd    : Wd;
    const float* bias = which ? bsd    : bd;
    const float* s    = which ? s_sent : s_word;
    float*       dst  = which ? g_sdec : g_dec;

    int n  = rem * 2 + (wid >> 2);
    int b0 = (wid & 3) * 4;

    const float4* wv = (const float4*)(W + (size_t)n * N);
    float4 w0 = wv[lane], w1 = wv[32+lane], w2 = wv[64+lane], w3 = wv[96+lane];
    float bn = bias[n];

    float a0, a1, a2, a3;
    {
        const float4* s0 = (const float4*)(s + (size_t)(b0 + 0) * N);
        const float4* s1 = (const float4*)(s + (size_t)(b0 + 1) * N);
        const float4* s2 = (const float4*)(s + (size_t)(b0 + 2) * N);
        const float4* s3 = (const float4*)(s + (size_t)(b0 + 3) * N);
        a0 = dot4(s0[lane],w0)+dot4(s0[32+lane],w1)+dot4(s0[64+lane],w2)+dot4(s0[96+lane],w3);
        a1 = dot4(s1[lane],w0)+dot4(s1[32+lane],w1)+dot4(s1[64+lane],w2)+dot4(s1[96+lane],w3);
        a2 = dot4(s2[lane],w0)+dot4(s2[32+lane],w1)+dot4(s2[64+lane],w2)+dot4(s2[96+lane],w3);
        a3 = dot4(s3[lane],w0)+dot4(s3[32+lane],w1)+dot4(s3[64+lane],w2)+dot4(s3[96+lane],w3);
    }
#pragma unroll
    for (int o = 16; o; o >>= 1) {
        a0 += __shfl_xor_sync(0xffffffffu, a0, o);
        a1 += __shfl_xor_sync(0xffffffffu, a1, o);
        a2 += __shfl_xor_sync(0xffffffffu, a2, o);
        a3 += __shfl_xor_sync(0xffffffffu, a3, o);
    }
    if (lane == 0) {
        dst[(b0 + 0) * N + n] = a0 + bn;
        dst[(b0 + 1) * N + n] = a1 + bn;
        dst[(b0 + 2) * N + n] = a2 + bn;
        dst[(b0 + 3) * N + n] = a3 + bn;
    }
}

// ---------------------------------------------------------------------------
// Kernel 2 (fused, no waiting): blocks [0,512): 64 tokens of b.
//   Phase A (R10 scorer): warp owns 8 tokens in 4 batches of 2; operands in
//   smem; e -> e_sh + g_e; atomic segsum + per-b S.
//   Phase B: enc context over the SAME 64 tokens with unnormalized e;
//   atomicAdd partials into zeroed o_ct (scaled later by 1/S).
// blocks [512,528): full sentence path.
// ---------------------------------------------------------------------------
__global__ void __launch_bounds__(256, 4)
score_ctx(const float* __restrict__ feat,
          const float* __restrict__ enc,
          const float* __restrict__ v,
          const float* __restrict__ wc,
          const float* __restrict__ cov,
          const float* __restrict__ mask,
          const int* __restrict__ spos,
          const float* __restrict__ sfeat,
          const float* __restrict__ svw,
          const float* __restrict__ smask,
          const float* __restrict__ sout,
          float* __restrict__ o_sattn,
          float* __restrict__ o_sct,
          float* __restrict__ o_ct)
{
    int blk  = blockIdx.x;
    int tid  = threadIdx.x;
    int wid  = tid >> 5;
    int lane = tid & 31;

    if (blk < NSCORE) {
        __shared__ float4 s_d[N/4];      // dec slice (2KB)
        __shared__ float4 s_V[N/4];      // v         (2KB)
        __shared__ float4 s_w[N/4];      // w_c       (2KB)
        __shared__ int    pos[STK];
        __shared__ float  e_sh[STK];
        __shared__ float  warp_e[8];

        int b  = blk >> 5;               // 32 blocks per b
        int t0 = (blk & 31) * 64;        // 64 tokens per block, warp owns 8

        {
            const float4* dv = (const float4*)(g_dec + (size_t)b * N);
            const float4* vv = (const float4*)v;
            const float4* wv = (const float4*)wc;
            if (tid < N/4) {
                s_d[tid] = dv[tid];
                s_V[tid] = vv[tid];
                s_w[tid] = wv[tid];
            } else {
                int i = tid - N/4;
                if (i < STK) pos[i] = spos[b * STK + i];
            }
        }
        __syncthreads();

        // ---------- Phase A: scores ----------
        float esum = 0.f;
#pragma unroll
        for (int tb = 0; tb < 8; tb += 2) {
            int tA = t0 + wid * 8 + tb;
            int gA = b * TK + tA;
            int gB = gA + 1;
            float cA = cov[gA];
            float cB = cov[gB];
            const float4* fA = (const float4*)(feat + (size_t)gA * N);
            const float4* fB = (const float4*)(feat + (size_t)gB * N);
            float4 A0 = fA[lane], A1 = fA[32+lane], A2 = fA[64+lane], A3 = fA[96+lane];
            float4 B0 = fB[lane], B1 = fB[32+lane], B2 = fB[64+lane], B3 = fB[96+lane];

            float accA = 0.f, accB = 0.f;
#pragma unroll
            for (int i = 0; i < 4; i++) {
                float4 fa = (i==0)?A0:(i==1)?A1:(i==2)?A2:A3;
                float4 fb = (i==0)?B0:(i==1)?B1:(i==2)?B2:B3;
                int j = i * 32 + lane;
                float4 d = s_d[j];
                float4 V = s_V[j];
                float4 w = s_w[j];
                accA = fmaf(tanh_fast(fa.x + d.x + cA * w.x), V.x, accA);
                accB = fmaf(tanh_fast(fb.x + d.x + cB * w.x), V.x, accB);
                accA = fmaf(tanh_fast(fa.y + d.y + cA * w.y), V.y, accA);
                accB = fmaf(tanh_fast(fb.y + d.y + cB * w.y), V.y, accB);
                accA = fmaf(tanh_fast(fa.z + d.z + cA * w.z), V.z, accA);
                accB = fmaf(tanh_fast(fb.z + d.z + cB * w.z), V.z, accB);
                accA = fmaf(tanh_fast(fa.w + d.w + cA * w.w), V.w, accA);
                accB = fmaf(tanh_fast(fb.w + d.w + cB * w.w), V.w, accB);
            }
#pragma unroll
            for (int o = 16; o; o >>= 1) {
                accA += __shfl_xor_sync(0xffffffffu, accA, o);
                accB += __shfl_xor_sync(0xffffffffu, accB, o);
            }
            if (lane == 0) {
                float eA = expf(accA) * mask[gA];
                float eB = expf(accB) * mask[gB];
                g_e[gA] = eA;
                g_e[gB] = eB;
                e_sh[wid * 8 + tb]     = eA;
                e_sh[wid * 8 + tb + 1] = eB;
                int sA = seg_of(tA, pos);
                int sB = seg_of(tA + 1, pos);
                if (sA < STK) atomicAdd(&g_segsum[b * STK + sA], eA);
                if (sB < STK) atomicAdd(&g_segsum[b * STK + sB], eB);
                esum += eA + eB;
            }
        }
        if (lane == 0) warp_e[wid] = esum;
        __syncthreads();
        if (tid == 0) {
            float s = 0.f;
#pragma unroll
            for (int i = 0; i < 8; i++) s += warp_e[i];
            atomicAdd(&g_S[b], s);
        }

        // ---------- Phase B: unnormalized context over own 64 tokens ----------
        int grp = tid >> 7;              // 0/1: two 16-token chunks per half
        int col = tid & 127;             // float4 column
        const float4* ev = (const float4*)enc;
        float4 acc = make_float4(0.f, 0.f, 0.f, 0.f);
#pragma unroll
        for (int h = 0; h < 2; h++) {
            int tb = h * 32 + grp * 16;
            size_t base = ((size_t)b * TK + t0 + tb) * (N / 4) + col;
#pragma unroll
            for (int i = 0; i < 16; i++) {
                float e = e_sh[tb + i];
                float4 x = ev[base + (size_t)i * (N / 4)];
                acc.x = fmaf(e, x.x, acc.x);
                acc.y = fmaf(e, x.y, acc.y);
                acc.z = fmaf(e, x.z, acc.z);
                acc.w = fmaf(e, x.w, acc.w);
            }
        }
        float* o = o_ct + (size_t)b * N + col * 4;
        atomicAdd(o + 0, acc.x);
        atomicAdd(o + 1, acc.y);
        atomicAdd(o + 2, acc.z);
        atomicAdd(o + 3, acc.w);
    } else {
        // ---------------- sentence path: one block per b ----------------
        __shared__ float se[STK];
        int b = blk - NSCORE;

        const float4* dv = (const float4*)(g_sdec + (size_t)b * N);
        const float4* vv = (const float4*)svw;
        for (int t = wid; t < STK; t += 8) {
            const float4* fv = (const float4*)(sfeat + ((size_t)b * STK + t) * N);
            float acc = 0.f;
#pragma unroll
            for (int i = 0; i < 4; i++) {
                int j = i * 32 + lane;
                float4 f = fv[j];
                float4 d = dv[j];
                float4 V = vv[j];
                acc = fmaf(tanh_fast(f.x + d.x), V.x,
                      fmaf(tanh_fast(f.y + d.y), V.y,
                      fmaf(tanh_fast(f.z + d.z), V.z,
                      fmaf(tanh_fast(f.w + d.w), V.w, acc))));
            }
            acc = warp_sum(acc);
            if (lane == 0) se[t] = acc;
        }
        __syncthreads();

        if (wid == 0) {
            float s0 = se[lane], s1 = se[lane + 32];
            float m = warp_max(fmaxf(s0, s1));
            float e0 = expf(s0 - m), e1 = expf(s1 - m);
            float inv = 1.f / warp_sum(e0 + e1);
            float a0 = e0 * inv * smask[b * STK + lane];
            float a1 = e1 * inv * smask[b * STK + 32 + lane];
            float inv2 = 1.f / warp_sum(a0 + a1);
            a0 *= inv2; a1 *= inv2;
            se[lane] = a0; se[lane + 32] = a1;
            o_sattn[b * STK + lane]      = a0;
            o_sattn[b * STK + 32 + lane] = a1;
        }
        __syncthreads();

        for (int n = tid; n < N; n += 256) {
            float acc = 0.f;
#pragma unroll 8
            for (int t = 0; t < STK; t++)
                acc = fmaf(se[t], sout[((size_t)b * STK + t) * N + n], acc);
            o_sct[b * N + n] = acc;
        }
    }
}

// ---------------------------------------------------------------------------
// Kernel 3: finalize. grid 64 x 512. Block = (b, quarter of TK):
//   attn = e/S; coverage = cov + e/segsum * sattn.
//   quarter==0 blocks also scale c_t by 1/S.
// ---------------------------------------------------------------------------
__global__ void finalize(const float* __restrict__ cov,
                         const int* __restrict__ spos,
                         const float* __restrict__ sattn,
                         float* __restrict__ o_attn,
                         float* __restrict__ o_cov,
                         float* __restrict__ o_ct)
{
    __shared__ int   pos[STK];
    __shared__ float ssum[STK];
    __shared__ float satt[STK];

    int blk = blockIdx.x;           // 64 blocks
    int b   = blk >> 2;
    int q   = blk & 3;
    int tid = threadIdx.x;

    if (tid < STK) {
        pos[tid]  = spos[b * STK + tid];
        ssum[tid] = g_segsum[b * STK + tid];
        satt[tid] = sattn[b * STK + tid];
    }
    __syncthreads();

    float invS = 1.f / g_S[b];

    int t = q * 512 + tid;
    float e = g_e[b * TK + t];
    o_attn[b * TK + t] = e * invS;
    int sg = seg_of(t, pos);
    float sw = (sg < STK) ? e / ssum[sg] * satt[sg] : 0.f;
    o_cov[b * TK + t] = cov[b * TK + t] + sw;

    if (q == 0)
        o_ct[b * N + tid] *= invS;
}

// ---------------------------------------------------------------------------
extern "C" void kernel_launch(void* const* d_in, const int* in_sizes, int n_in,
                              void* d_out, int out_size)
{
    const float* s_t_hat  = (const float*)d_in[0];
    const int*   spos     = (const int*)  d_in[1];
    const float* enc_out  = (const float*)d_in[2];
    const float* enc_feat = (const float*)d_in[3];
    const float* mask     = (const float*)d_in[4];
    const float* s_sent   = (const float*)d_in[5];
    const float* sout     = (const float*)d_in[6];
    const float* sfeat    = (const float*)d_in[7];
    const float* smask    = (const float*)d_in[8];
    const float* cov      = (const float*)d_in[9];
    const float* Wd       = (const float*)d_in[10];
    const float* bd       = (const float*)d_in[11];
    const float* vw       = (const float*)d_in[12];
    const float* Wsd      = (const float*)d_in[13];
    const float* bsd      = (const float*)d_in[14];
    const float* svw      = (const float*)d_in[15];
    const float* wc       = (const float*)d_in[16];

    float* out     = (float*)d_out;
    float* o_ct    = out + OFF_CT;
    float* o_attn  = out + OFF_ATTN;
    float* o_cov   = out + OFF_COV;
    float* o_sct   = out + OFF_SCT;
    float* o_sattn = out + OFF_SATTN;

    dec_gemm<<<512, 256>>>(s_t_hat, Wd, bd, s_sent, Wsd, bsd, o_ct);

    score_ctx<<<NSCORE + NSENT, 256>>>(enc_feat, enc_out, vw, wc, cov, mask, spos,
                                       sfeat, svw, smask, sout,
                                       o_sattn, o_sct, o_ct);

    finalize<<<64, 512>>>(cov, spos, o_sattn, o_attn, o_cov, o_ct);
}

// round 15
// speedup vs baseline: 1.4510x; 1.0981x over previous
#include <cuda_runtime.h>
#include <math.h>

#define B   16
#define TK  2048
#define STK 64
#define N   512

// output layout (flattened tuple, row-major each)
#define OFF_CT    0
#define OFF_ATTN  (B*N)
#define OFF_COV   (OFF_ATTN + B*TK)
#define OFF_SCT   (OFF_COV + B*TK)
#define OFF_SATTN (OFF_SCT + B*N)

#define SC_SPLIT  32               // scorer blocks per b (64 tokens each)
#define NSCORE    (B*SC_SPLIT)     // 512
#define NSENT     16

// scratch
__device__ float g_dec[B*N];       // word decoder features
__device__ float g_sdec[B*N];      // sentence decoder features
__device__ float g_e[B*TK];        // exp(score)*mask
__device__ float g_S[B];           // sum of e per b
__device__ float g_segsum[B*STK];  // per-sentence sums of e

__device__ __forceinline__ float warp_sum(float v)
{
#pragma unroll
    for (int o = 16; o; o >>= 1) v += __shfl_xor_sync(0xffffffffu, v, o);
    return v;
}
__device__ __forceinline__ float warp_max(float v)
{
#pragma unroll
    for (int o = 16; o; o >>= 1) v = fmaxf(v, __shfl_xor_sync(0xffffffffu, v, o));
    return v;
}
__device__ __forceinline__ float dot4(float4 a, float4 b)
{
    return fmaf(a.x, b.x, fmaf(a.y, b.y, fmaf(a.z, b.z, a.w * b.w)));
}
__device__ __forceinline__ float tanh_fast(float x)
{
    float y;
    asm("tanh.approx.f32 %0, %1;" : "=f"(y) : "f"(x));
    return y;
}
__device__ __forceinline__ int seg_of(int t, const int* pos)
{
    int lo = 0, hi = STK;
    while (lo < hi) {
        int mid = (lo + hi) >> 1;
        if (pos[mid] <= t) lo = mid + 1; else hi = mid;
    }
    return lo;
}

// ---------------------------------------------------------------------------
// Kernel 1: both dec GEMMs. grid 1024, 256 thr. Warp: 1 row x 2 b.
// Also zeroes g_S, g_segsum, o_ct (distributed).
// ---------------------------------------------------------------------------
__global__ void dec_gemm(const float* __restrict__ s_word,
                         const float* __restrict__ Wd,
                         const float* __restrict__ bd,
                         const float* __restrict__ s_sent,
                         const float* __restrict__ Wsd,
                         const float* __restrict__ bsd,
                         float* __restrict__ o_ct)
{
    int blk  = blockIdx.x;            // 0..1023
    int tid  = threadIdx.x;
    int wid  = tid >> 5;
    int lane = tid & 31;

    int g = blk * 256 + tid;
    if (g < B * N)   o_ct[g] = 0.f;
    if (g < B * STK) g_segsum[g] = 0.f;
    if (g < B)       g_S[g] = 0.f;

    int which = blk >> 9;             // 0 word, 1 sentence
    int rem   = blk & 511;            // 512 blocks per which; 1 row each
    const float* W    = which ? Wsd    : Wd;
    const float* bias = which ? bsd    : bd;
    const float* s    = which ? s_sent : s_word;
    float*       dst  = which ? g_sdec : g_dec;

    int n  = rem;                     // row index
    int b0 = wid * 2;                 // batch pair

    const float4* wv = (const float4*)(W + (size_t)n * N);
    float4 w0 = wv[lane], w1 = wv[32+lane], w2 = wv[64+lane], w3 = wv[96+lane];
    float bn = bias[n];

    float a0, a1;
    {
        const float4* s0 = (const float4*)(s + (size_t)(b0 + 0) * N);
        const float4* s1 = (const float4*)(s + (size_t)(b0 + 1) * N);
        a0 = dot4(s0[lane],w0)+dot4(s0[32+lane],w1)+dot4(s0[64+lane],w2)+dot4(s0[96+lane],w3);
        a1 = dot4(s1[lane],w0)+dot4(s1[32+lane],w1)+dot4(s1[64+lane],w2)+dot4(s1[96+lane],w3);
    }
#pragma unroll
    for (int o = 16; o; o >>= 1) {
        a0 += __shfl_xor_sync(0xffffffffu, a0, o);
        a1 += __shfl_xor_sync(0xffffffffu, a1, o);
    }
    if (lane == 0) {
        dst[(b0 + 0) * N + n] = a0 + bn;
        dst[(b0 + 1) * N + n] = a1 + bn;
    }
}

// ---------------------------------------------------------------------------
// Kernel 2 (fused): blocks [0,512): 64 tokens of b.
//   Phase A: scorer (warp x 8 tokens, batches of 2, operands in smem);
//            e -> e_sh + g_e; atomic segsum + per-b S.
//   Phase B: unnormalized enc context over the SAME 64 tokens; atomicAdd
//            partials into zeroed o_ct. Streaming loads (__ldcs) on the
//            two single-use 64MB tensors.
// blocks [512,528): full sentence path.
// ---------------------------------------------------------------------------
__global__ void __launch_bounds__(256, 4)
score_ctx(const float* __restrict__ feat,
          const float* __restrict__ enc,
          const float* __restrict__ v,
          const float* __restrict__ wc,
          const float* __restrict__ cov,
          const float* __restrict__ mask,
          const int* __restrict__ spos,
          const float* __restrict__ sfeat,
          const float* __restrict__ svw,
          const float* __restrict__ smask,
          const float* __restrict__ sout,
          float* __restrict__ o_sattn,
          float* __restrict__ o_sct,
          float* __restrict__ o_ct)
{
    int blk  = blockIdx.x;
    int tid  = threadIdx.x;
    int wid  = tid >> 5;
    int lane = tid & 31;

    if (blk < NSCORE) {
        __shared__ float4 s_d[N/4];      // dec slice (2KB)
        __shared__ float4 s_V[N/4];      // v         (2KB)
        __shared__ float4 s_w[N/4];      // w_c       (2KB)
        __shared__ int    pos[STK];
        __shared__ float  e_sh[STK];
        __shared__ float  warp_e[8];

        int b  = blk >> 5;               // 32 blocks per b
        int t0 = (blk & 31) * 64;        // 64 tokens per block, warp owns 8

        {
            const float4* dv = (const float4*)(g_dec + (size_t)b * N);
            const float4* vv = (const float4*)v;
            const float4* wv = (const float4*)wc;
            if (tid < N/4) {
                s_d[tid] = dv[tid];
                s_V[tid] = vv[tid];
                s_w[tid] = wv[tid];
            } else {
                int i = tid - N/4;
                if (i < STK) pos[i] = spos[b * STK + i];
            }
        }
        __syncthreads();

        // ---------- Phase A: scores ----------
        float esum = 0.f;
#pragma unroll
        for (int tb = 0; tb < 8; tb += 2) {
            int tA = t0 + wid * 8 + tb;
            int gA = b * TK + tA;
            int gB = gA + 1;
            float cA = cov[gA];
            float cB = cov[gB];
            const float4* fA = (const float4*)(feat + (size_t)gA * N);
            const float4* fB = (const float4*)(feat + (size_t)gB * N);
            float4 A0 = __ldcs(fA + lane),    A1 = __ldcs(fA + 32 + lane);
            float4 A2 = __ldcs(fA + 64 + lane), A3 = __ldcs(fA + 96 + lane);
            float4 B0 = __ldcs(fB + lane),    B1 = __ldcs(fB + 32 + lane);
            float4 B2 = __ldcs(fB + 64 + lane), B3 = __ldcs(fB + 96 + lane);

            float accA = 0.f, accB = 0.f;
#pragma unroll
            for (int i = 0; i < 4; i++) {
                float4 fa = (i==0)?A0:(i==1)?A1:(i==2)?A2:A3;
                float4 fb = (i==0)?B0:(i==1)?B1:(i==2)?B2:B3;
                int j = i * 32 + lane;
                float4 d = s_d[j];
                float4 V = s_V[j];
                float4 w = s_w[j];
                accA = fmaf(tanh_fast(fa.x + d.x + cA * w.x), V.x, accA);
                accB = fmaf(tanh_fast(fb.x + d.x + cB * w.x), V.x, accB);
                accA = fmaf(tanh_fast(fa.y + d.y + cA * w.y), V.y, accA);
                accB = fmaf(tanh_fast(fb.y + d.y + cB * w.y), V.y, accB);
                accA = fmaf(tanh_fast(fa.z + d.z + cA * w.z), V.z, accA);
                accB = fmaf(tanh_fast(fb.z + d.z + cB * w.z), V.z, accB);
                accA = fmaf(tanh_fast(fa.w + d.w + cA * w.w), V.w, accA);
                accB = fmaf(tanh_fast(fb.w + d.w + cB * w.w), V.w, accB);
            }
#pragma unroll
            for (int o = 16; o; o >>= 1) {
                accA += __shfl_xor_sync(0xffffffffu, accA, o);
                accB += __shfl_xor_sync(0xffffffffu, accB, o);
            }
            if (lane == 0) {
                float eA = expf(accA) * mask[gA];
                float eB = expf(accB) * mask[gB];
                g_e[gA] = eA;
                g_e[gB] = eB;
                e_sh[wid * 8 + tb]     = eA;
                e_sh[wid * 8 + tb + 1] = eB;
                int sA = seg_of(tA, pos);
                int sB = seg_of(tA + 1, pos);
                if (sA < STK) atomicAdd(&g_segsum[b * STK + sA], eA);
                if (sB < STK) atomicAdd(&g_segsum[b * STK + sB], eB);
                esum += eA + eB;
            }
        }
        if (lane == 0) warp_e[wid] = esum;
        __syncthreads();
        if (tid == 0) {
            float s = 0.f;
#pragma unroll
            for (int i = 0; i < 8; i++) s += warp_e[i];
            atomicAdd(&g_S[b], s);
        }

        // ---------- Phase B: unnormalized context over own 64 tokens ----------
        int grp = tid >> 7;              // 0/1: two 16-token chunks per half
        int col = tid & 127;             // float4 column
        const float4* ev = (const float4*)enc;
        float4 acc = make_float4(0.f, 0.f, 0.f, 0.f);
#pragma unroll
        for (int h = 0; h < 2; h++) {
            int tb = h * 32 + grp * 16;
            size_t base = ((size_t)b * TK + t0 + tb) * (N / 4) + col;
#pragma unroll
            for (int i = 0; i < 16; i++) {
                float e = e_sh[tb + i];
                float4 x = __ldcs(ev + base + (size_t)i * (N / 4));
                acc.x = fmaf(e, x.x, acc.x);
                acc.y = fmaf(e, x.y, acc.y);
                acc.z = fmaf(e, x.z, acc.z);
                acc.w = fmaf(e, x.w, acc.w);
            }
        }
        float* o = o_ct + (size_t)b * N + col * 4;
        atomicAdd(o + 0, acc.x);
        atomicAdd(o + 1, acc.y);
        atomicAdd(o + 2, acc.z);
        atomicAdd(o + 3, acc.w);
    } else {
        // ---------------- sentence path: one block per b ----------------
        __shared__ float se[STK];
        int b = blk - NSCORE;

        const float4* dv = (const float4*)(g_sdec + (size_t)b * N);
        const float4* vv = (const float4*)svw;
        for (int t = wid; t < STK; t += 8) {
            const float4* fv = (const float4*)(sfeat + ((size_t)b * STK + t) * N);
            float acc = 0.f;
#pragma unroll
            for (int i = 0; i < 4; i++) {
                int j = i * 32 + lane;
                float4 f = __ldcs(fv + j);
                float4 d = dv[j];
                float4 V = vv[j];
                acc = fmaf(tanh_fast(f.x + d.x), V.x,
                      fmaf(tanh_fast(f.y + d.y), V.y,
                      fmaf(tanh_fast(f.z + d.z), V.z,
                      fmaf(tanh_fast(f.w + d.w), V.w, acc))));
            }
            acc = warp_sum(acc);
            if (lane == 0) se[t] = acc;
        }
        __syncthreads();

        if (wid == 0) {
            float s0 = se[lane], s1 = se[lane + 32];
            float m = warp_max(fmaxf(s0, s1));
            float e0 = expf(s0 - m), e1 = expf(s1 - m);
            float inv = 1.f / warp_sum(e0 + e1);
            float a0 = e0 * inv * smask[b * STK + lane];
            float a1 = e1 * inv * smask[b * STK + 32 + lane];
            float inv2 = 1.f / warp_sum(a0 + a1);
            a0 *= inv2; a1 *= inv2;
            se[lane] = a0; se[lane + 32] = a1;
            o_sattn[b * STK + lane]      = a0;
            o_sattn[b * STK + 32 + lane] = a1;
        }
        __syncthreads();

        for (int n = tid; n < N; n += 256) {
            float acc = 0.f;
#pragma unroll 8
            for (int t = 0; t < STK; t++)
                acc = fmaf(se[t], __ldcs(sout + ((size_t)b * STK + t) * N + n), acc);
            o_sct[b * N + n] = acc;
        }
    }
}

// ---------------------------------------------------------------------------
// Kernel 3: finalize. grid 128 x 256. Block = (b, eighth of TK):
//   attn = e/S; coverage = cov + e/segsum * sattn.
//   eighth==0 blocks also scale c_t by 1/S (2 elems per thread).
// ---------------------------------------------------------------------------
__global__ void finalize(const float* __restrict__ cov,
                         const int* __restrict__ spos,
                         const float* __restrict__ sattn,
                         float* __restrict__ o_attn,
                         float* __restrict__ o_cov,
                         float* __restrict__ o_ct)
{
    __shared__ int   pos[STK];
    __shared__ float ssum[STK];
    __shared__ float satt[STK];

    int blk = blockIdx.x;           // 128 blocks
    int b   = blk >> 3;
    int q   = blk & 7;
    int tid = threadIdx.x;          // 256

    if (tid < STK) {
        pos[tid]  = spos[b * STK + tid];
        ssum[tid] = g_segsum[b * STK + tid];
        satt[tid] = sattn[b * STK + tid];
    }
    __syncthreads();

    float invS = 1.f / g_S[b];

    int t = q * 256 + tid;
    float e = g_e[b * TK + t];
    o_attn[b * TK + t] = e * invS;
    int sg = seg_of(t, pos);
    float sw = (sg < STK) ? e / ssum[sg] * satt[sg] : 0.f;
    o_cov[b * TK + t] = cov[b * TK + t] + sw;

    if (q == 0) {
        o_ct[b * N + tid]       *= invS;
        o_ct[b * N + 256 + tid] *= invS;
    }
}

// ---------------------------------------------------------------------------
extern "C" void kernel_launch(void* const* d_in, const int* in_sizes, int n_in,
                              void* d_out, int out_size)
{
    const float* s_t_hat  = (const float*)d_in[0];
    const int*   spos     = (const int*)  d_in[1];
    const float* enc_out  = (const float*)d_in[2];
    const float* enc_feat = (const float*)d_in[3];
    const float* mask     = (const float*)d_in[4];
    const float* s_sent   = (const float*)d_in[5];
    const float* sout     = (const float*)d_in[6];
    const float* sfeat    = (const float*)d_in[7];
    const float* smask    = (const float*)d_in[8];
    const float* cov      = (const float*)d_in[9];
    const float* Wd       = (const float*)d_in[10];
    const float* bd       = (const float*)d_in[11];
    const float* vw       = (const float*)d_in[12];
    const float* Wsd      = (const float*)d_in[13];
    const float* bsd      = (const float*)d_in[14];
    const float* svw      = (const float*)d_in[15];
    const float* wc       = (const float*)d_in[16];

    float* out     = (float*)d_out;
    float* o_ct    = out + OFF_CT;
    float* o_attn  = out + OFF_ATTN;
    float* o_cov   = out + OFF_COV;
    float* o_sct   = out + OFF_SCT;
    float* o_sattn = out + OFF_SATTN;

    dec_gemm<<<1024, 256>>>(s_t_hat, Wd, bd, s_sent, Wsd, bsd, o_ct);

    score_ctx<<<NSCORE + NSENT, 256>>>(enc_feat, enc_out, vw, wc, cov, mask, spos,
                                       sfeat, svw, smask, sout,
                                       o_sattn, o_sct, o_ct);

    finalize<<<128, 256>>>(cov, spos, o_sattn, o_attn, o_cov, o_ct);
}

// round 16
// speedup vs baseline: 1.5252x; 1.0511x over previous
#include <cuda_runtime.h>
#include <math.h>

#define B   16
#define TK  2048
#define STK 64
#define N   512

// output layout (flattened tuple, row-major each)
#define OFF_CT    0
#define OFF_ATTN  (B*N)
#define OFF_COV   (OFF_ATTN + B*TK)
#define OFF_SCT   (OFF_COV + B*TK)
#define OFF_SATTN (OFF_SCT + B*N)

#define SC_SPLIT  32               // scorer blocks per b (64 tokens each)
#define NSCORE    (B*SC_SPLIT)     // 512
#define NSENT     16

// scratch
__device__ float g_dec[B*N];       // word decoder features
__device__ float g_sdec[B*N];      // sentence decoder features
__device__ float g_e[B*TK];        // exp(score)*mask
__device__ float g_S[B];           // sum of e per b
__device__ float g_segsum[B*STK];  // per-sentence sums of e

__device__ __forceinline__ float warp_sum(float v)
{
#pragma unroll
    for (int o = 16; o; o >>= 1) v += __shfl_xor_sync(0xffffffffu, v, o);
    return v;
}
__device__ __forceinline__ float warp_max(float v)
{
#pragma unroll
    for (int o = 16; o; o >>= 1) v = fmaxf(v, __shfl_xor_sync(0xffffffffu, v, o));
    return v;
}
__device__ __forceinline__ float dot4(float4 a, float4 b)
{
    return fmaf(a.x, b.x, fmaf(a.y, b.y, fmaf(a.z, b.z, a.w * b.w)));
}
__device__ __forceinline__ float tanh_fast(float x)
{
    float y;
    asm("tanh.approx.f32 %0, %1;" : "=f"(y) : "f"(x));
    return y;
}
__device__ __forceinline__ int seg_of(int t, const int* pos)
{
    int lo = 0, hi = STK;
    while (lo < hi) {
        int mid = (lo + hi) >> 1;
        if (pos[mid] <= t) lo = mid + 1; else hi = mid;
    }
    return lo;
}

// ---------------------------------------------------------------------------
// Kernel 1: both dec GEMMs (R14 body). grid 512, 256 thr. Warp: 1 row x 4 b.
// Also zeroes g_S, g_segsum, o_ct (distributed). Triggers PDL early.
// ---------------------------------------------------------------------------
__global__ void dec_gemm(const float* __restrict__ s_word,
                         const float* __restrict__ Wd,
                         const float* __restrict__ bd,
                         const float* __restrict__ s_sent,
                         const float* __restrict__ Wsd,
                         const float* __restrict__ bsd,
                         float* __restrict__ o_ct)
{
    cudaTriggerProgrammaticLaunchCompletion();

    int blk  = blockIdx.x;            // 0..511
    int tid  = threadIdx.x;
    int wid  = tid >> 5;
    int lane = tid & 31;

    int g = blk * 256 + tid;
    if (g < B * N)   o_ct[g] = 0.f;
    if (g < B * STK) g_segsum[g] = 0.f;
    if (g < B)       g_S[g] = 0.f;

    int which = blk >> 8;             // 0 word, 1 sentence
    int rem   = blk & 255;
    const float* W    = which ? Wsd    : Wd;
    const float* bias = which ? bsd    : bd;
    const float* s    = which ? s_sent : s_word;
    float*       dst  = which ? g_sdec : g_dec;

    int n  = rem * 2 + (wid >> 2);
    int b0 = (wid & 3) * 4;

    const float4* wv = (const float4*)(W + (size_t)n * N);
    float4 w0 = wv[lane], w1 = wv[32+lane], w2 = wv[64+lane], w3 = wv[96+lane];
    float bn = bias[n];

    float a0, a1, a2, a3;
    {
        const float4* s0 = (const float4*)(s + (size_t)(b0 + 0) * N);
        const float4* s1 = (const float4*)(s + (size_t)(b0 + 1) * N);
        const float4* s2 = (const float4*)(s + (size_t)(b0 + 2) * N);
        const float4* s3 = (const float4*)(s + (size_t)(b0 + 3) * N);
        a0 = dot4(s0[lane],w0)+dot4(s0[32+lane],w1)+dot4(s0[64+lane],w2)+dot4(s0[96+lane],w3);
        a1 = dot4(s1[lane],w0)+dot4(s1[32+lane],w1)+dot4(s1[64+lane],w2)+dot4(s1[96+lane],w3);
        a2 = dot4(s2[lane],w0)+dot4(s2[32+lane],w1)+dot4(s2[64+lane],w2)+dot4(s2[96+lane],w3);
        a3 = dot4(s3[lane],w0)+dot4(s3[32+lane],w1)+dot4(s3[64+lane],w2)+dot4(s3[96+lane],w3);
    }
#pragma unroll
    for (int o = 16; o; o >>= 1) {
        a0 += __shfl_xor_sync(0xffffffffu, a0, o);
        a1 += __shfl_xor_sync(0xffffffffu, a1, o);
        a2 += __shfl_xor_sync(0xffffffffu, a2, o);
        a3 += __shfl_xor_sync(0xffffffffu, a3, o);
    }
    if (lane == 0) {
        dst[(b0 + 0) * N + n] = a0 + bn;
        dst[(b0 + 1) * N + n] = a1 + bn;
        dst[(b0 + 2) * N + n] = a2 + bn;
        dst[(b0 + 3) * N + n] = a3 + bn;
    }
}

// ---------------------------------------------------------------------------
// Kernel 2 (fused, PDL secondary): blocks [0,512): 64 tokens of b.
//   Prologue stages input-only operands (v, wc, pos), THEN grid-dep-sync,
//   then stages g_dec slice. Phase A scorer; Phase B unnormalized context.
// blocks [512,528): sentence path. Triggers PDL for finalize early.
// ---------------------------------------------------------------------------
__global__ void __launch_bounds__(256, 4)
score_ctx(const float* __restrict__ feat,
          const float* __restrict__ enc,
          const float* __restrict__ v,
          const float* __restrict__ wc,
          const float* __restrict__ cov,
          const float* __restrict__ mask,
          const int* __restrict__ spos,
          const float* __restrict__ sfeat,
          const float* __restrict__ svw,
          const float* __restrict__ smask,
          const float* __restrict__ sout,
          float* __restrict__ o_sattn,
          float* __restrict__ o_sct,
          float* __restrict__ o_ct)
{
    cudaTriggerProgrammaticLaunchCompletion();

    int blk  = blockIdx.x;
    int tid  = threadIdx.x;
    int wid  = tid >> 5;
    int lane = tid & 31;

    if (blk < NSCORE) {
        __shared__ float4 s_d[N/4];      // dec slice (2KB)
        __shared__ float4 s_V[N/4];      // v         (2KB)
        __shared__ float4 s_w[N/4];      // w_c       (2KB)
        __shared__ int    pos[STK];
        __shared__ float  e_sh[STK];
        __shared__ float  warp_e[8];

        int b  = blk >> 5;               // 32 blocks per b
        int t0 = (blk & 31) * 64;        // 64 tokens per block, warp owns 8

        // stage input-only operands (overlaps with dec_gemm completion)
        {
            const float4* vv = (const float4*)v;
            const float4* wv = (const float4*)wc;
            if (tid < N/4) {
                s_V[tid] = vv[tid];
                s_w[tid] = wv[tid];
            } else {
                int i = tid - N/4;
                if (i < STK) pos[i] = spos[b * STK + i];
            }
        }

        // wait for dec_gemm (g_dec + zeroed accumulators)
        cudaGridDependencySynchronize();

        if (tid < N/4) {
            const float4* dv = (const float4*)(g_dec + (size_t)b * N);
            s_d[tid] = dv[tid];
        }
        __syncthreads();

        // ---------- Phase A: scores ----------
        float esum = 0.f;
#pragma unroll
        for (int tb = 0; tb < 8; tb += 2) {
            int tA = t0 + wid * 8 + tb;
            int gA = b * TK + tA;
            int gB = gA + 1;
            float cA = cov[gA];
            float cB = cov[gB];
            const float4* fA = (const float4*)(feat + (size_t)gA * N);
            const float4* fB = (const float4*)(feat + (size_t)gB * N);
            float4 A0 = __ldcs(fA + lane),      A1 = __ldcs(fA + 32 + lane);
            float4 A2 = __ldcs(fA + 64 + lane), A3 = __ldcs(fA + 96 + lane);
            float4 B0 = __ldcs(fB + lane),      B1 = __ldcs(fB + 32 + lane);
            float4 B2 = __ldcs(fB + 64 + lane), B3 = __ldcs(fB + 96 + lane);

            float accA = 0.f, accB = 0.f;
#pragma unroll
            for (int i = 0; i < 4; i++) {
                float4 fa = (i==0)?A0:(i==1)?A1:(i==2)?A2:A3;
                float4 fb = (i==0)?B0:(i==1)?B1:(i==2)?B2:B3;
                int j = i * 32 + lane;
                float4 d = s_d[j];
                float4 V = s_V[j];
                float4 w = s_w[j];
                accA = fmaf(tanh_fast(fa.x + d.x + cA * w.x), V.x, accA);
                accB = fmaf(tanh_fast(fb.x + d.x + cB * w.x), V.x, accB);
                accA = fmaf(tanh_fast(fa.y + d.y + cA * w.y), V.y, accA);
                accB = fmaf(tanh_fast(fb.y + d.y + cB * w.y), V.y, accB);
                accA = fmaf(tanh_fast(fa.z + d.z + cA * w.z), V.z, accA);
                accB = fmaf(tanh_fast(fb.z + d.z + cB * w.z), V.z, accB);
                accA = fmaf(tanh_fast(fa.w + d.w + cA * w.w), V.w, accA);
                accB = fmaf(tanh_fast(fb.w + d.w + cB * w.w), V.w, accB);
            }
#pragma unroll
            for (int o = 16; o; o >>= 1) {
                accA += __shfl_xor_sync(0xffffffffu, accA, o);
                accB += __shfl_xor_sync(0xffffffffu, accB, o);
            }
            if (lane == 0) {
                float eA = expf(accA) * mask[gA];
                float eB = expf(accB) * mask[gB];
                g_e[gA] = eA;
                g_e[gB] = eB;
                e_sh[wid * 8 + tb]     = eA;
                e_sh[wid * 8 + tb + 1] = eB;
                int sA = seg_of(tA, pos);
                int sB = seg_of(tA + 1, pos);
                if (sA < STK) atomicAdd(&g_segsum[b * STK + sA], eA);
                if (sB < STK) atomicAdd(&g_segsum[b * STK + sB], eB);
                esum += eA + eB;
            }
        }
        if (lane == 0) warp_e[wid] = esum;
        __syncthreads();
        if (tid == 0) {
            float s = 0.f;
#pragma unroll
            for (int i = 0; i < 8; i++) s += warp_e[i];
            atomicAdd(&g_S[b], s);
        }

        // ---------- Phase B: unnormalized context over own 64 tokens ----------
        int grp = tid >> 7;              // 0/1: two 16-token chunks per half
        int col = tid & 127;             // float4 column
        const float4* ev = (const float4*)enc;
        float4 acc = make_float4(0.f, 0.f, 0.f, 0.f);
#pragma unroll
        for (int h = 0; h < 2; h++) {
            int tb = h * 32 + grp * 16;
            size_t base = ((size_t)b * TK + t0 + tb) * (N / 4) + col;
#pragma unroll
            for (int i = 0; i < 16; i++) {
                float e = e_sh[tb + i];
                float4 x = __ldcs(ev + base + (size_t)i * (N / 4));
                acc.x = fmaf(e, x.x, acc.x);
                acc.y = fmaf(e, x.y, acc.y);
                acc.z = fmaf(e, x.z, acc.z);
                acc.w = fmaf(e, x.w, acc.w);
            }
        }
        float* o = o_ct + (size_t)b * N + col * 4;
        atomicAdd(o + 0, acc.x);
        atomicAdd(o + 1, acc.y);
        atomicAdd(o + 2, acc.z);
        atomicAdd(o + 3, acc.w);
    } else {
        // ---------------- sentence path: one block per b ----------------
        __shared__ float se[STK];
        int b = blk - NSCORE;

        cudaGridDependencySynchronize();   // needs g_sdec

        const float4* dv = (const float4*)(g_sdec + (size_t)b * N);
        const float4* vv = (const float4*)svw;
        for (int t = wid; t < STK; t += 8) {
            const float4* fv = (const float4*)(sfeat + ((size_t)b * STK + t) * N);
            float acc = 0.f;
#pragma unroll
            for (int i = 0; i < 4; i++) {
                int j = i * 32 + lane;
                float4 f = __ldcs(fv + j);
                float4 d = dv[j];
                float4 V = vv[j];
                acc = fmaf(tanh_fast(f.x + d.x), V.x,
                      fmaf(tanh_fast(f.y + d.y), V.y,
                      fmaf(tanh_fast(f.z + d.z), V.z,
                      fmaf(tanh_fast(f.w + d.w), V.w, acc))));
            }
            acc = warp_sum(acc);
            if (lane == 0) se[t] = acc;
        }
        __syncthreads();

        if (wid == 0) {
            float s0 = se[lane], s1 = se[lane + 32];
            float m = warp_max(fmaxf(s0, s1));
            float e0 = expf(s0 - m), e1 = expf(s1 - m);
            float inv = 1.f / warp_sum(e0 + e1);
            float a0 = e0 * inv * smask[b * STK + lane];
            float a1 = e1 * inv * smask[b * STK + 32 + lane];
            float inv2 = 1.f / warp_sum(a0 + a1);
            a0 *= inv2; a1 *= inv2;
            se[lane] = a0; se[lane + 32] = a1;
            o_sattn[b * STK + lane]      = a0;
            o_sattn[b * STK + 32 + lane] = a1;
        }
        __syncthreads();

        for (int n = tid; n < N; n += 256) {
            float acc = 0.f;
#pragma unroll 8
            for (int t = 0; t < STK; t++)
                acc = fmaf(se[t], __ldcs(sout + ((size_t)b * STK + t) * N + n), acc);
            o_sct[b * N + n] = acc;
        }
    }
}

// ---------------------------------------------------------------------------
// Kernel 3: finalize (PDL secondary). grid 128 x 256. Block = (b, eighth):
//   attn = e/S; coverage = cov + e/segsum * sattn; eighth==0 scales c_t.
// ---------------------------------------------------------------------------
__global__ void finalize(const float* __restrict__ cov,
                         const int* __restrict__ spos,
                         const float* __restrict__ sattn,
                         float* __restrict__ o_attn,
                         float* __restrict__ o_cov,
                         float* __restrict__ o_ct)
{
    __shared__ int   pos[STK];
    __shared__ float ssum[STK];
    __shared__ float satt[STK];

    int blk = blockIdx.x;           // 128 blocks
    int b   = blk >> 3;
    int q   = blk & 7;
    int tid = threadIdx.x;          // 256

    // input-only staging overlaps with score_ctx drain
    if (tid < STK) pos[tid] = spos[b * STK + tid];

    cudaGridDependencySynchronize();

    if (tid < STK) {
        ssum[tid] = g_segsum[b * STK + tid];
        satt[tid] = sattn[b * STK + tid];
    }
    __syncthreads();

    float invS = 1.f / g_S[b];

    int t = q * 256 + tid;
    float e = g_e[b * TK + t];
    o_attn[b * TK + t] = e * invS;
    int sg = seg_of(t, pos);
    float sw = (sg < STK) ? e / ssum[sg] * satt[sg] : 0.f;
    o_cov[b * TK + t] = cov[b * TK + t] + sw;

    if (q == 0) {
        o_ct[b * N + tid]       *= invS;
        o_ct[b * N + 256 + tid] *= invS;
    }
}

// ---------------------------------------------------------------------------
extern "C" void kernel_launch(void* const* d_in, const int* in_sizes, int n_in,
                              void* d_out, int out_size)
{
    const float* s_t_hat  = (const float*)d_in[0];
    const int*   spos     = (const int*)  d_in[1];
    const float* enc_out  = (const float*)d_in[2];
    const float* enc_feat = (const float*)d_in[3];
    const float* mask     = (const float*)d_in[4];
    const float* s_sent   = (const float*)d_in[5];
    const float* sout     = (const float*)d_in[6];
    const float* sfeat    = (const float*)d_in[7];
    const float* smask    = (const float*)d_in[8];
    const float* cov      = (const float*)d_in[9];
    const float* Wd       = (const float*)d_in[10];
    const float* bd       = (const float*)d_in[11];
    const float* vw       = (const float*)d_in[12];
    const float* Wsd      = (const float*)d_in[13];
    const float* bsd      = (const float*)d_in[14];
    const float* svw      = (const float*)d_in[15];
    const float* wc       = (const float*)d_in[16];

    float* out     = (float*)d_out;
    float* o_ct    = out + OFF_CT;
    float* o_attn  = out + OFF_ATTN;
    float* o_cov   = out + OFF_COV;
    float* o_sct   = out + OFF_SCT;
    float* o_sattn = out + OFF_SATTN;

    dec_gemm<<<512, 256>>>(s_t_hat, Wd, bd, s_sent, Wsd, bsd, o_ct);

    {
        cudaLaunchConfig_t cfg = {};
        cfg.gridDim  = dim3(NSCORE + NSENT);
        cfg.blockDim = dim3(256);
        cudaLaunchAttribute attr[1];
        attr[0].id = cudaLaunchAttributeProgrammaticStreamSerialization;
        attr[0].val.programmaticStreamSerializationAllowed = 1;
        cfg.attrs = attr;
        cfg.numAttrs = 1;
        cudaLaunchKernelEx(&cfg, score_ctx,
                           enc_feat, enc_out, vw, wc, cov, mask, spos,
                           sfeat, svw, smask, sout, o_sattn, o_sct, o_ct);
    }
    {
        cudaLaunchConfig_t cfg = {};
        cfg.gridDim  = dim3(128);
        cfg.blockDim = dim3(256);
        cudaLaunchAttribute attr[1];
        attr[0].id = cudaLaunchAttributeProgrammaticStreamSerialization;
        attr[0].val.programmaticStreamSerializationAllowed = 1;
        cfg.attrs = attr;
        cfg.numAttrs = 1;
        cudaLaunchKernelEx(&cfg, finalize,
                           cov, spos, o_sattn, o_attn, o_cov, o_ct);
    }
}

// round 17
// speedup vs baseline: 1.5264x; 1.0008x over previous
#include <cuda_runtime.h>
#include <math.h>

#define B   16
#define TK  2048
#define STK 64
#define N   512

// output layout (flattened tuple, row-major each)
#define OFF_CT    0
#define OFF_ATTN  (B*N)
#define OFF_COV   (OFF_ATTN + B*TK)
#define OFF_SCT   (OFF_COV + B*TK)
#define OFF_SATTN (OFF_SCT + B*N)

#define SC_SPLIT  32               // scorer blocks per b (64 tokens each)
#define NSCORE    (B*SC_SPLIT)     // 512
#define NSENT     16

// scratch
__device__ float g_dec[B*N];       // word decoder features
__device__ float g_sdec[B*N];      // sentence decoder features
__device__ float g_e[B*TK];        // exp(score)*mask
__device__ float g_S[B];           // sum of e per b
__device__ float g_segsum[B*STK];  // per-sentence sums of e

__device__ __forceinline__ float warp_sum(float v)
{
#pragma unroll
    for (int o = 16; o; o >>= 1) v += __shfl_xor_sync(0xffffffffu, v, o);
    return v;
}
__device__ __forceinline__ float warp_max(float v)
{
#pragma unroll
    for (int o = 16; o; o >>= 1) v = fmaxf(v, __shfl_xor_sync(0xffffffffu, v, o));
    return v;
}
__device__ __forceinline__ float dot4(float4 a, float4 b)
{
    return fmaf(a.x, b.x, fmaf(a.y, b.y, fmaf(a.z, b.z, a.w * b.w)));
}
__device__ __forceinline__ float tanh_fast(float x)
{
    float y;
    asm("tanh.approx.f32 %0, %1;" : "=f"(y) : "f"(x));
    return y;
}
__device__ __forceinline__ int seg_of(int t, const int* pos)
{
    int lo = 0, hi = STK;
    while (lo < hi) {
        int mid = (lo + hi) >> 1;
        if (pos[mid] <= t) lo = mid + 1; else hi = mid;
    }
    return lo;
}

// ---------------------------------------------------------------------------
// Kernel 1: both dec GEMMs. grid 512, 256 thr. Warp: 1 row x 4 b.
// Also zeroes g_S, g_segsum, o_ct (distributed).
// PDL trigger at the END — after ALL writes the dependent grid reads.
// ---------------------------------------------------------------------------
__global__ void dec_gemm(const float* __restrict__ s_word,
                         const float* __restrict__ Wd,
                         const float* __restrict__ bd,
                         const float* __restrict__ s_sent,
                         const float* __restrict__ Wsd,
                         const float* __restrict__ bsd,
                         float* __restrict__ o_ct)
{
    int blk  = blockIdx.x;            // 0..511
    int tid  = threadIdx.x;
    int wid  = tid >> 5;
    int lane = tid & 31;

    int g = blk * 256 + tid;
    if (g < B * N)   o_ct[g] = 0.f;
    if (g < B * STK) g_segsum[g] = 0.f;
    if (g < B)       g_S[g] = 0.f;

    int which = blk >> 8;             // 0 word, 1 sentence
    int rem   = blk & 255;
    const float* W    = which ? Wsd    : Wd;
    const float* bias = which ? bsd    : bd;
    const float* s    = which ? s_sent : s_word;
    float*       dst  = which ? g_sdec : g_dec;

    int n  = rem * 2 + (wid >> 2);
    int b0 = (wid & 3) * 4;

    const float4* wv = (const float4*)(W + (size_t)n * N);
    float4 w0 = wv[lane], w1 = wv[32+lane], w2 = wv[64+lane], w3 = wv[96+lane];
    float bn = bias[n];

    float a0, a1, a2, a3;
    {
        const float4* s0 = (const float4*)(s + (size_t)(b0 + 0) * N);
        const float4* s1 = (const float4*)(s + (size_t)(b0 + 1) * N);
        const float4* s2 = (const float4*)(s + (size_t)(b0 + 2) * N);
        const float4* s3 = (const float4*)(s + (size_t)(b0 + 3) * N);
        a0 = dot4(s0[lane],w0)+dot4(s0[32+lane],w1)+dot4(s0[64+lane],w2)+dot4(s0[96+lane],w3);
        a1 = dot4(s1[lane],w0)+dot4(s1[32+lane],w1)+dot4(s1[64+lane],w2)+dot4(s1[96+lane],w3);
        a2 = dot4(s2[lane],w0)+dot4(s2[32+lane],w1)+dot4(s2[64+lane],w2)+dot4(s2[96+lane],w3);
        a3 = dot4(s3[lane],w0)+dot4(s3[32+lane],w1)+dot4(s3[64+lane],w2)+dot4(s3[96+lane],w3);
    }
#pragma unroll
    for (int o = 16; o; o >>= 1) {
        a0 += __shfl_xor_sync(0xffffffffu, a0, o);
        a1 += __shfl_xor_sync(0xffffffffu, a1, o);
        a2 += __shfl_xor_sync(0xffffffffu, a2, o);
        a3 += __shfl_xor_sync(0xffffffffu, a3, o);
    }
    if (lane == 0) {
        dst[(b0 + 0) * N + n] = a0 + bn;
        dst[(b0 + 1) * N + n] = a1 + bn;
        dst[(b0 + 2) * N + n] = a2 + bn;
        dst[(b0 + 3) * N + n] = a3 + bn;
    }

    // all dependent-visible writes done -> release the dependent grid
    cudaTriggerProgrammaticLaunchCompletion();
}

// ---------------------------------------------------------------------------
// Kernel 2 (fused, PDL secondary): blocks [0,512): 64 tokens of b.
//   Prologue stages input-only operands (v, wc, pos), THEN grid-dep-sync,
//   then stages g_dec slice. Phase A scorer; Phase B unnormalized context.
// blocks [512,528): sentence path. PDL trigger at END (after all writes).
// ---------------------------------------------------------------------------
__global__ void __launch_bounds__(256, 4)
score_ctx(const float* __restrict__ feat,
          const float* __restrict__ enc,
          const float* __restrict__ v,
          const float* __restrict__ wc,
          const float* __restrict__ cov,
          const float* __restrict__ mask,
          const int* __restrict__ spos,
          const float* __restrict__ sfeat,
          const float* __restrict__ svw,
          const float* __restrict__ smask,
          const float* __restrict__ sout,
          float* __restrict__ o_sattn,
          float* __restrict__ o_sct,
          float* __restrict__ o_ct)
{
    int blk  = blockIdx.x;
    int tid  = threadIdx.x;
    int wid  = tid >> 5;
    int lane = tid & 31;

    if (blk < NSCORE) {
        __shared__ float4 s_d[N/4];      // dec slice (2KB)
        __shared__ float4 s_V[N/4];      // v         (2KB)
        __shared__ float4 s_w[N/4];      // w_c       (2KB)
        __shared__ int    pos[STK];
        __shared__ float  e_sh[STK];
        __shared__ float  warp_e[8];

        int b  = blk >> 5;               // 32 blocks per b
        int t0 = (blk & 31) * 64;        // 64 tokens per block, warp owns 8

        // stage input-only operands (overlaps with dec_gemm tail)
        {
            const float4* vv = (const float4*)v;
            const float4* wv = (const float4*)wc;
            if (tid < N/4) {
                s_V[tid] = vv[tid];
                s_w[tid] = wv[tid];
            } else {
                int i = tid - N/4;
                if (i < STK) pos[i] = spos[b * STK + i];
            }
        }

        // wait for dec_gemm (g_dec + zeroed accumulators)
        cudaGridDependencySynchronize();

        if (tid < N/4) {
            const float4* dv = (const float4*)(g_dec + (size_t)b * N);
            s_d[tid] = dv[tid];
        }
        __syncthreads();

        // ---------- Phase A: scores ----------
        float esum = 0.f;
#pragma unroll
        for (int tb = 0; tb < 8; tb += 2) {
            int tA = t0 + wid * 8 + tb;
            int gA = b * TK + tA;
            int gB = gA + 1;
            float cA = cov[gA];
            float cB = cov[gB];
            const float4* fA = (const float4*)(feat + (size_t)gA * N);
            const float4* fB = (const float4*)(feat + (size_t)gB * N);
            float4 A0 = __ldcs(fA + lane),      A1 = __ldcs(fA + 32 + lane);
            float4 A2 = __ldcs(fA + 64 + lane), A3 = __ldcs(fA + 96 + lane);
            float4 B0 = __ldcs(fB + lane),      B1 = __ldcs(fB + 32 + lane);
            float4 B2 = __ldcs(fB + 64 + lane), B3 = __ldcs(fB + 96 + lane);

            float accA = 0.f, accB = 0.f;
#pragma unroll
            for (int i = 0; i < 4; i++) {
                float4 fa = (i==0)?A0:(i==1)?A1:(i==2)?A2:A3;
                float4 fb = (i==0)?B0:(i==1)?B1:(i==2)?B2:B3;
                int j = i * 32 + lane;
                float4 d = s_d[j];
                float4 V = s_V[j];
                float4 w = s_w[j];
                accA = fmaf(tanh_fast(fa.x + d.x + cA * w.x), V.x, accA);
                accB = fmaf(tanh_fast(fb.x + d.x + cB * w.x), V.x, accB);
                accA = fmaf(tanh_fast(fa.y + d.y + cA * w.y), V.y, accA);
                accB = fmaf(tanh_fast(fb.y + d.y + cB * w.y), V.y, accB);
                accA = fmaf(tanh_fast(fa.z + d.z + cA * w.z), V.z, accA);
                accB = fmaf(tanh_fast(fb.z + d.z + cB * w.z), V.z, accB);
                accA = fmaf(tanh_fast(fa.w + d.w + cA * w.w), V.w, accA);
                accB = fmaf(tanh_fast(fb.w + d.w + cB * w.w), V.w, accB);
            }
#pragma unroll
            for (int o = 16; o; o >>= 1) {
                accA += __shfl_xor_sync(0xffffffffu, accA, o);
                accB += __shfl_xor_sync(0xffffffffu, accB, o);
            }
            if (lane == 0) {
                float eA = expf(accA) * mask[gA];
                float eB = expf(accB) * mask[gB];
                g_e[gA] = eA;
                g_e[gB] = eB;
                e_sh[wid * 8 + tb]     = eA;
                e_sh[wid * 8 + tb + 1] = eB;
                int sA = seg_of(tA, pos);
                int sB = seg_of(tA + 1, pos);
                if (sA < STK) atomicAdd(&g_segsum[b * STK + sA], eA);
                if (sB < STK) atomicAdd(&g_segsum[b * STK + sB], eB);
                esum += eA + eB;
            }
        }
        if (lane == 0) warp_e[wid] = esum;
        __syncthreads();
        if (tid == 0) {
            float s = 0.f;
#pragma unroll
            for (int i = 0; i < 8; i++) s += warp_e[i];
            atomicAdd(&g_S[b], s);
        }

        // ---------- Phase B: unnormalized context over own 64 tokens ----------
        int grp = tid >> 7;              // 0/1: two 16-token chunks per half
        int col = tid & 127;             // float4 column
        const float4* ev = (const float4*)enc;
        float4 acc = make_float4(0.f, 0.f, 0.f, 0.f);
#pragma unroll
        for (int h = 0; h < 2; h++) {
            int tb = h * 32 + grp * 16;
            size_t base = ((size_t)b * TK + t0 + tb) * (N / 4) + col;
#pragma unroll
            for (int i = 0; i < 16; i++) {
                float e = e_sh[tb + i];
                float4 x = __ldcs(ev + base + (size_t)i * (N / 4));
                acc.x = fmaf(e, x.x, acc.x);
                acc.y = fmaf(e, x.y, acc.y);
                acc.z = fmaf(e, x.z, acc.z);
                acc.w = fmaf(e, x.w, acc.w);
            }
        }
        float* o = o_ct + (size_t)b * N + col * 4;
        atomicAdd(o + 0, acc.x);
        atomicAdd(o + 1, acc.y);
        atomicAdd(o + 2, acc.z);
        atomicAdd(o + 3, acc.w);
    } else {
        // ---------------- sentence path: one block per b ----------------
        __shared__ float se[STK];
        int b = blk - NSCORE;

        cudaGridDependencySynchronize();   // needs g_sdec

        const float4* dv = (const float4*)(g_sdec + (size_t)b * N);
        const float4* vv = (const float4*)svw;
        for (int t = wid; t < STK; t += 8) {
            const float4* fv = (const float4*)(sfeat + ((size_t)b * STK + t) * N);
            float acc = 0.f;
#pragma unroll
            for (int i = 0; i < 4; i++) {
                int j = i * 32 + lane;
                float4 f = __ldcs(fv + j);
                float4 d = dv[j];
                float4 V = vv[j];
                acc = fmaf(tanh_fast(f.x + d.x), V.x,
                      fmaf(tanh_fast(f.y + d.y), V.y,
                      fmaf(tanh_fast(f.z + d.z), V.z,
                      fmaf(tanh_fast(f.w + d.w), V.w, acc))));
            }
            acc = warp_sum(acc);
            if (lane == 0) se[t] = acc;
        }
        __syncthreads();

        if (wid == 0) {
            float s0 = se[lane], s1 = se[lane + 32];
            float m = warp_max(fmaxf(s0, s1));
            float e0 = expf(s0 - m), e1 = expf(s1 - m);
            float inv = 1.f / warp_sum(e0 + e1);
            float a0 = e0 * inv * smask[b * STK + lane];
            float a1 = e1 * inv * smask[b * STK + 32 + lane];
            float inv2 = 1.f / warp_sum(a0 + a1);
            a0 *= inv2; a1 *= inv2;
            se[lane] = a0; se[lane + 32] = a1;
            o_sattn[b * STK + lane]      = a0;
            o_sattn[b * STK + 32 + lane] = a1;
        }
        __syncthreads();

        for (int n = tid; n < N; n += 256) {
            float acc = 0.f;
#pragma unroll 8
            for (int t = 0; t < STK; t++)
                acc = fmaf(se[t], __ldcs(sout + ((size_t)b * STK + t) * N + n), acc);
            o_sct[b * N + n] = acc;
        }
    }

    // all dependent-visible writes done -> release finalize
    cudaTriggerProgrammaticLaunchCompletion();
}

// ---------------------------------------------------------------------------
// Kernel 3: finalize (PDL secondary). grid 128 x 256. Block = (b, eighth):
//   attn = e/S; coverage = cov + e/segsum * sattn; eighth==0 scales c_t.
// ---------------------------------------------------------------------------
__global__ void finalize(const float* __restrict__ cov,
                         const int* __restrict__ spos,
                         const float* __restrict__ sattn,
                         float* __restrict__ o_attn,
                         float* __restrict__ o_cov,
                         float* __restrict__ o_ct)
{
    __shared__ int   pos[STK];
    __shared__ float ssum[STK];
    __shared__ float satt[STK];

    int blk = blockIdx.x;           // 128 blocks
    int b   = blk >> 3;
    int q   = blk & 7;
    int tid = threadIdx.x;          // 256

    // input-only staging overlaps with score_ctx drain
    if (tid < STK) pos[tid] = spos[b * STK + tid];

    cudaGridDependencySynchronize();

    if (tid < STK) {
        ssum[tid] = g_segsum[b * STK + tid];
        satt[tid] = sattn[b * STK + tid];
    }
    __syncthreads();

    float invS = 1.f / g_S[b];

    int t = q * 256 + tid;
    float e = g_e[b * TK + t];
    o_attn[b * TK + t] = e * invS;
    int sg = seg_of(t, pos);
    float sw = (sg < STK) ? e / ssum[sg] * satt[sg] : 0.f;
    o_cov[b * TK + t] = cov[b * TK + t] + sw;

    if (q == 0) {
        o_ct[b * N + tid]       *= invS;
        o_ct[b * N + 256 + tid] *= invS;
    }
}

// ---------------------------------------------------------------------------
extern "C" void kernel_launch(void* const* d_in, const int* in_sizes, int n_in,
                              void* d_out, int out_size)
{
    const float* s_t_hat  = (const float*)d_in[0];
    const int*   spos     = (const int*)  d_in[1];
    const float* enc_out  = (const float*)d_in[2];
    const float* enc_feat = (const float*)d_in[3];
    const float* mask     = (const float*)d_in[4];
    const float* s_sent   = (const float*)d_in[5];
    const float* sout     = (const float*)d_in[6];
    const float* sfeat    = (const float*)d_in[7];
    const float* smask    = (const float*)d_in[8];
    const float* cov      = (const float*)d_in[9];
    const float* Wd       = (const float*)d_in[10];
    const float* bd       = (const float*)d_in[11];
    const float* vw       = (const float*)d_in[12];
    const float* Wsd      = (const float*)d_in[13];
    const float* bsd      = (const float*)d_in[14];
    const float* svw      = (const float*)d_in[15];
    const float* wc       = (const float*)d_in[16];

    float* out     = (float*)d_out;
    float* o_ct    = out + OFF_CT;
    float* o_attn  = out + OFF_ATTN;
    float* o_cov   = out + OFF_COV;
    float* o_sct   = out + OFF_SCT;
    float* o_sattn = out + OFF_SATTN;

    dec_gemm<<<512, 256>>>(s_t_hat, Wd, bd, s_sent, Wsd, bsd, o_ct);

    {
        cudaLaunchConfig_t cfg = {};
        cfg.gridDim  = dim3(NSCORE + NSENT);
        cfg.blockDim = dim3(256);
        cudaLaunchAttribute attr[1];
        attr[0].id = cudaLaunchAttributeProgrammaticStreamSerialization;
        attr[0].val.programmaticStreamSerializationAllowed = 1;
        cfg.attrs = attr;
        cfg.numAttrs = 1;
        cudaLaunchKernelEx(&cfg, score_ctx,
                           enc_feat, enc_out, vw, wc, cov, mask, spos,
                           sfeat, svw, smask, sout, o_sattn, o_sct, o_ct);
    }
    {
        cudaLaunchConfig_t cfg = {};
        cfg.gridDim  = dim3(128);
        cfg.blockDim = dim3(256);
        cudaLaunchAttribute attr[1];
        attr[0].id = cudaLaunchAttributeProgrammaticStreamSerialization;
        attr[0].val.programmaticStreamSerializationAllowed = 1;
        cfg.attrs = attr;
        cfg.numAttrs = 1;
        cudaLaunchKernelEx(&cfg, finalize,
                           cov, spos, o_sattn, o_attn, o_cov, o_ct);
    }
}